// round 8
// baseline (speedup 1.0000x reference)
#include <cuda_runtime.h>
#include <cuda_bf16.h>
#include <cstdint>

#define NMAX 100000
#define EMAX 600000

// Scratch (static device globals — allocation-free per harness rules)
__device__ __align__(16) float g_ylr[NMAX * 128];  // projected [y_l | y_r]
__device__ __align__(16) float g_x[NMAX * 64];     // layer activations
__device__ __align__(16) unsigned g_xh[NMAX * 64]; // emb hi bf16 (2 per uint)
__device__ __align__(16) unsigned g_xl[NMAX * 64]; // emb lo bf16
__device__ __align__(16) unsigned short g_wth[128 * 128];  // W0 hi bf16, n-major [n][k]
__device__ __align__(16) unsigned short g_wtl[128 * 128];  // W0 lo bf16, n-major [n][k]
__device__ int g_cnt[NMAX];
__device__ int g_off[NMAX];
__device__ int g_cur[NMAX];
__device__ int g_esrc[EMAX];
__device__ int g_bsum[512];

// ---------------------------------------------------------------------------
// cp.async + packed fma helpers (used by the f32x2 GEMM only)
// ---------------------------------------------------------------------------
__device__ __forceinline__ void cp_async16(uint32_t dst, const void* src, int src_bytes) {
    asm volatile("cp.async.cg.shared.global [%0], [%1], 16, %2;\n"
                 :: "r"(dst), "l"(src), "r"(src_bytes));
}
__device__ __forceinline__ void cp_commit() { asm volatile("cp.async.commit_group;\n"); }
template <int N>
__device__ __forceinline__ void cp_wait() { asm volatile("cp.async.wait_group %0;\n" :: "n"(N)); }

__device__ __forceinline__ void fma_x2(unsigned long long& acc, unsigned long long a2,
                                       unsigned long long b2) {
    asm("fma.rn.f32x2 %0, %1, %2, %0;" : "+l"(acc) : "l"(a2), "l"(b2));
}
__device__ __forceinline__ unsigned long long dup_f32(float a) {
    unsigned long long r;
    asm("mov.b64 %0, {%1, %1};" : "=l"(r) : "f"(a));
    return r;
}

// ---------------------------------------------------------------------------
// CSR build
// ---------------------------------------------------------------------------
__global__ void zero_int(int* __restrict__ p, int n) {
    int i = blockIdx.x * blockDim.x + threadIdx.x;
    if (i < n) p[i] = 0;
}

__global__ void hist_kernel(const int* __restrict__ dst, int* __restrict__ cnt, int E) {
    int i = blockIdx.x * blockDim.x + threadIdx.x;
    if (i < E) atomicAdd(&cnt[dst[i]], 1);
}

__device__ __forceinline__ int block_exscan_512(int v, int tid, int* warp_sums, int* total) {
    int lane = tid & 31, wid = tid >> 5;
    int inc = v;
#pragma unroll
    for (int st = 1; st < 32; st <<= 1) {
        int t = __shfl_up_sync(0xFFFFFFFFu, inc, st);
        if (lane >= st) inc += t;
    }
    if (lane == 31) warp_sums[wid] = inc;
    __syncthreads();
    if (wid == 0) {
        int ws = (lane < 16) ? warp_sums[lane] : 0;
#pragma unroll
        for (int st = 1; st < 16; st <<= 1) {
            int t = __shfl_up_sync(0xFFFFFFFFu, ws, st);
            if (lane >= st) ws += t;
        }
        if (lane < 16) warp_sums[lane] = ws;
    }
    __syncthreads();
    int base = (wid > 0) ? warp_sums[wid - 1] : 0;
    if (total) *total = warp_sums[15];
    return base + inc - v;
}

__global__ void scan_block(const int* __restrict__ cnt, int* __restrict__ off,
                           int* __restrict__ bsum, int n) {
    __shared__ int ws[16];
    int i = blockIdx.x * 512 + threadIdx.x;
    int v = (i < n) ? cnt[i] : 0;
    int total;
    int ex = block_exscan_512(v, threadIdx.x, ws, &total);
    if (i < n) off[i] = ex;
    if (threadIdx.x == 0) bsum[blockIdx.x] = total;
}

__global__ void scan_sums(int* __restrict__ bsum, int nb) {
    __shared__ int ws[16];
    int v = (threadIdx.x < nb) ? bsum[threadIdx.x] : 0;
    int ex = block_exscan_512(v, threadIdx.x, ws, nullptr);
    if (threadIdx.x < nb) bsum[threadIdx.x] = ex;
}

__global__ void scan_add(int* __restrict__ off, const int* __restrict__ bsum,
                         int* __restrict__ cur, int n) {
    int i = blockIdx.x * 512 + threadIdx.x;
    if (i < n) {
        int o = off[i] + bsum[blockIdx.x];
        off[i] = o;
        cur[i] = o;
    }
}

__global__ void fill_kernel(const int* __restrict__ src, const int* __restrict__ dst,
                            int* __restrict__ cur, int* __restrict__ esrc, int E) {
    int e = blockIdx.x * blockDim.x + threadIdx.x;
    if (e < E) {
        int p = atomicAdd(&cur[dst[e]], 1);
        esrc[p] = src[e];
    }
}

// ---------------------------------------------------------------------------
// bf16 split conversions for the layer-0 tensor-core GEMM
// ---------------------------------------------------------------------------
__device__ __forceinline__ unsigned pack_bf16(float a, float b) {
    __nv_bfloat162 h;
    h.x = __float2bfloat16(a);
    h.y = __float2bfloat16(b);
    return *reinterpret_cast<unsigned*>(&h);
}

__global__ void cvt_x_kernel(const float4* __restrict__ x, uint2* __restrict__ xh,
                             uint2* __restrict__ xl, int n4) {
    int i = blockIdx.x * blockDim.x + threadIdx.x;
    if (i >= n4) return;
    float4 v = x[i];
    __nv_bfloat16 h0 = __float2bfloat16(v.x), h1 = __float2bfloat16(v.y);
    __nv_bfloat16 h2 = __float2bfloat16(v.z), h3 = __float2bfloat16(v.w);
    float r0 = v.x - __bfloat162float(h0), r1 = v.y - __bfloat162float(h1);
    float r2 = v.z - __bfloat162float(h2), r3 = v.w - __bfloat162float(h3);
    uint2 ph, pl;
    __nv_bfloat162 t;
    t.x = h0; t.y = h1; ph.x = *reinterpret_cast<unsigned*>(&t);
    t.x = h2; t.y = h3; ph.y = *reinterpret_cast<unsigned*>(&t);
    pl.x = pack_bf16(r0, r1);
    pl.y = pack_bf16(r2, r3);
    xh[i] = ph;
    xl[i] = pl;
}

// W0 combined [k=128][n=128] -> transposed n-major bf16 hi/lo: wt[n*128 + k]
__global__ void cvt_w_kernel(const float* __restrict__ wl, const float* __restrict__ wr,
                             unsigned short* __restrict__ wth, unsigned short* __restrict__ wtl) {
    int i = blockIdx.x * blockDim.x + threadIdx.x;
    if (i >= 128 * 128) return;
    int nn = i >> 7, k = i & 127;
    float w = (nn < 64) ? wl[k * 64 + nn] : wr[k * 64 + (nn - 64)];
    __nv_bfloat16 h = __float2bfloat16(w);
    __nv_bfloat16 l = __float2bfloat16(w - __bfloat162float(h));
    wth[i] = *reinterpret_cast<unsigned short*>(&h);
    wtl[i] = *reinterpret_cast<unsigned short*>(&l);
}

// ---------------------------------------------------------------------------
// layer-0 tensor-core GEMM: ylr[n x 128] = X[n x 128] @ W[128 x 128]
// 3-term bf16 split, fp32 accum, mma.m16n8k16. Explicit LDS fragment loads
// (PTX ISA thread mappings), no ldmatrix, no cp.async: single staged tile.
// Block: 256 thr (8 warps = 4m x 2n), BM=128, full K resident in smem.
// ---------------------------------------------------------------------------
__device__ __forceinline__ void mma16816(float* d, const unsigned* a,
                                         unsigned b0, unsigned b1) {
    asm volatile(
        "mma.sync.aligned.m16n8k16.row.col.f32.bf16.bf16.f32 "
        "{%0,%1,%2,%3}, {%4,%5,%6,%7}, {%8,%9}, {%0,%1,%2,%3};"
        : "+f"(d[0]), "+f"(d[1]), "+f"(d[2]), "+f"(d[3])
        : "r"(a[0]), "r"(a[1]), "r"(a[2]), "r"(a[3]), "r"(b0), "r"(b1));
}

__global__ void __launch_bounds__(256)
mma_proj0(const unsigned short* __restrict__ xh, const unsigned short* __restrict__ xl,
          const unsigned short* __restrict__ wth, const unsigned short* __restrict__ wtl,
          float* __restrict__ ylr, int n) {
    constexpr int S = 136;  // smem row stride in halves (272B; 68 words == 4 mod 32)
    extern __shared__ __align__(16) unsigned short smu[];
    unsigned short* sXh = smu;              // [128][S]
    unsigned short* sXl = sXh + 128 * S;
    unsigned short* sWh = sXl + 128 * S;    // n-major [n][k]
    unsigned short* sWl = sWh + 128 * S;

    const int tid = threadIdx.x;
    const int lane = tid & 31;
    const int warp = tid >> 5;
    const int warpm = warp >> 1;   // 0..3: 32 rows each
    const int warpn = warp & 1;    // 0..1: 64 cols each
    const int nb = blockIdx.x * 128;
    const int mrem = n - nb;

    // stage everything: 128 rows x 16 uint4-chunks per array
    for (int idx = tid; idx < 128 * 16; idx += 256) {
        int r = idx >> 4, c = (idx & 15) * 8;  // c: half offset (0,8,...,120)
        uint4 vh = make_uint4(0, 0, 0, 0), vl = vh;
        if (r < mrem) {
            vh = *reinterpret_cast<const uint4*>(&xh[(size_t)(nb + r) * 128 + c]);
            vl = *reinterpret_cast<const uint4*>(&xl[(size_t)(nb + r) * 128 + c]);
        }
        *reinterpret_cast<uint4*>(&sXh[r * S + c]) = vh;
        *reinterpret_cast<uint4*>(&sXl[r * S + c]) = vl;
        *reinterpret_cast<uint4*>(&sWh[r * S + c]) =
            *reinterpret_cast<const uint4*>(&wth[r * 128 + c]);
        *reinterpret_cast<uint4*>(&sWl[r * S + c]) =
            *reinterpret_cast<const uint4*>(&wtl[r * 128 + c]);
    }
    __syncthreads();

    const int g = lane >> 2;        // 0..7
    const int t2 = (lane & 3) * 2;  // 0,2,4,6

    float acc[2][8][4];
#pragma unroll
    for (int mt = 0; mt < 2; ++mt)
#pragma unroll
        for (int nt = 0; nt < 8; ++nt)
#pragma unroll
            for (int t = 0; t < 4; ++t) acc[mt][nt][t] = 0.f;

#pragma unroll
    for (int s = 0; s < 8; ++s) {
        const int k0 = s * 16;
        // A fragments (hi & lo). PTX m16n8k16 A map:
        // a0: (g, t2..t2+1)  a1: (g+8, ..)  a2: (g, t2+8..)  a3: (g+8, t2+8..)
        unsigned ah[2][4], al[2][4];
#pragma unroll
        for (int mt = 0; mt < 2; ++mt) {
            int r = warpm * 32 + mt * 16 + g;
            ah[mt][0] = *reinterpret_cast<const unsigned*>(&sXh[r * S + k0 + t2]);
            ah[mt][1] = *reinterpret_cast<const unsigned*>(&sXh[(r + 8) * S + k0 + t2]);
            ah[mt][2] = *reinterpret_cast<const unsigned*>(&sXh[r * S + k0 + t2 + 8]);
            ah[mt][3] = *reinterpret_cast<const unsigned*>(&sXh[(r + 8) * S + k0 + t2 + 8]);
            al[mt][0] = *reinterpret_cast<const unsigned*>(&sXl[r * S + k0 + t2]);
            al[mt][1] = *reinterpret_cast<const unsigned*>(&sXl[(r + 8) * S + k0 + t2]);
            al[mt][2] = *reinterpret_cast<const unsigned*>(&sXl[r * S + k0 + t2 + 8]);
            al[mt][3] = *reinterpret_cast<const unsigned*>(&sXl[(r + 8) * S + k0 + t2 + 8]);
        }
#pragma unroll
        for (int nt = 0; nt < 8; ++nt) {
            // B map: b0: (k=t2..t2+1, n=g)  b1: (k=t2+8.., n=g); W is n-major
            int nn = warpn * 64 + nt * 8 + g;
            unsigned bh0 = *reinterpret_cast<const unsigned*>(&sWh[nn * S + k0 + t2]);
            unsigned bh1 = *reinterpret_cast<const unsigned*>(&sWh[nn * S + k0 + t2 + 8]);
            unsigned bl0 = *reinterpret_cast<const unsigned*>(&sWl[nn * S + k0 + t2]);
            unsigned bl1 = *reinterpret_cast<const unsigned*>(&sWl[nn * S + k0 + t2 + 8]);
#pragma unroll
            for (int mt = 0; mt < 2; ++mt) {
                mma16816(acc[mt][nt], ah[mt], bh0, bh1);  // Xh*Wh
                mma16816(acc[mt][nt], al[mt], bh0, bh1);  // Xl*Wh
                mma16816(acc[mt][nt], ah[mt], bl0, bl1);  // Xh*Wl
            }
        }
    }

    // epilogue: D map — c0,c1: (g, t2..t2+1); c2,c3: (g+8, ..)
#pragma unroll
    for (int mt = 0; mt < 2; ++mt) {
#pragma unroll
        for (int nt = 0; nt < 8; ++nt) {
            int col = warpn * 64 + nt * 8 + t2;
            int node0 = nb + warpm * 32 + mt * 16 + g;
            int node1 = node0 + 8;
            if (node0 < n) {
                float2 v = make_float2(acc[mt][nt][0], acc[mt][nt][1]);
                *reinterpret_cast<float2*>(&ylr[(size_t)node0 * 128 + col]) = v;
            }
            if (node1 < n) {
                float2 v = make_float2(acc[mt][nt][2], acc[mt][nt][3]);
                *reinterpret_cast<float2*>(&ylr[(size_t)node1 * 128 + col]) = v;
            }
        }
    }
}

// ---------------------------------------------------------------------------
// projection GEMM (packed f32x2) — layer 1
// ---------------------------------------------------------------------------
template <int K, int NC, int BM, int BK, int MINBLK>
__global__ void __launch_bounds__((BM / 8) * (NC / 8), MINBLK)
sgemm_proj_x2(const float* __restrict__ x, const float* __restrict__ wl,
              const float* __restrict__ wr, float* __restrict__ ylr, int n) {
    constexpr int TM = 8;
    constexpr int PAD = 4;
    constexpr int F = NC / 2;
    constexpr int NTH = (BM / TM) * (NC / 8);
    constexpr int KT = K / BK;
    constexpr int XS = BK + PAD;

    extern __shared__ float smf[];
    float* sX = smf;
    float* sB = smf + 2 * BM * XS;

    const int tid = threadIdx.x;
    const int nb = blockIdx.x * BM;
    const int mrem = n - nb;

    auto load_tile = [&](int kb, int buf) {
        const int k0 = kb * BK;
        float* sXb = sX + buf * BM * XS;
        float* sBb = sB + buf * BK * NC;
        for (int idx = tid; idx < BM * BK / 4; idx += NTH) {
            int m = idx / (BK / 4);
            int kc = idx % (BK / 4);
            uint32_t dst = (uint32_t)__cvta_generic_to_shared(&sXb[m * XS + kc * 4]);
            int mm = (m < mrem) ? m : 0;
            const float* src = x + (size_t)(nb + mm) * K + k0 + kc * 4;
            cp_async16(dst, src, (m < mrem) ? 16 : 0);
        }
        for (int idx = tid; idx < BK * NC / 4; idx += NTH) {
            int kr = idx / (NC / 4);
            int j = (idx % (NC / 4)) * 4;
            const float* src = (j < F) ? (wl + (size_t)(kr + k0) * F + j)
                                       : (wr + (size_t)(kr + k0) * F + (j - F));
            uint32_t dst = (uint32_t)__cvta_generic_to_shared(&sBb[kr * NC + j]);
            cp_async16(dst, src, 16);
        }
    };

    load_tile(0, 0);
    cp_commit();

    constexpr int CG = NC / 8;
    const int tj = tid % CG;
    const int ti = tid / CG;
    const int m0 = ti * TM;
    const int jA = tj * 4;
    const int jB = jA + F;

    unsigned long long acc[TM][4];
#pragma unroll
    for (int i = 0; i < TM; ++i)
#pragma unroll
        for (int t = 0; t < 4; ++t) acc[i][t] = 0ull;

    for (int kb = 0; kb < KT; ++kb) {
        if (kb + 1 < KT) {
            load_tile(kb + 1, (kb + 1) & 1);
            cp_commit();
            cp_wait<1>();
        } else {
            cp_wait<0>();
        }
        __syncthreads();

        const float* bx = sX + (kb & 1) * BM * XS;
        const float* bb = sB + (kb & 1) * BK * NC;
#pragma unroll
        for (int k = 0; k < BK; ++k) {
            ulonglong2 bp0 = *reinterpret_cast<const ulonglong2*>(&bb[k * NC + jA]);
            ulonglong2 bp1 = *reinterpret_cast<const ulonglong2*>(&bb[k * NC + jB]);
#pragma unroll
            for (int i = 0; i < TM; ++i) {
                unsigned long long a2 = dup_f32(bx[(m0 + i) * XS + k]);
                fma_x2(acc[i][0], a2, bp0.x);
                fma_x2(acc[i][1], a2, bp0.y);
                fma_x2(acc[i][2], a2, bp1.x);
                fma_x2(acc[i][3], a2, bp1.y);
            }
        }
        __syncthreads();
    }

#pragma unroll
    for (int i = 0; i < TM; ++i) {
        int node = nb + m0 + i;
        if (node < n) {
            ulonglong2 v0, v1;
            v0.x = acc[i][0]; v0.y = acc[i][1];
            v1.x = acc[i][2]; v1.y = acc[i][3];
            *reinterpret_cast<ulonglong2*>(&ylr[(size_t)node * NC + jA]) = v0;
            *reinterpret_cast<ulonglong2*>(&ylr[(size_t)node * NC + jB]) = v1;
        }
    }
}

// ---------------------------------------------------------------------------
// per-node projection for small layers
// ---------------------------------------------------------------------------
template <int K, int F>
__global__ void proj_pernode(const float* __restrict__ x, const float* __restrict__ wl,
                             const float* __restrict__ wr, float* __restrict__ ylr, int n) {
    constexpr int NC = 2 * F;
    __shared__ float sB[K * NC];
    for (int i = threadIdx.x; i < K * NC; i += blockDim.x) {
        int k = i / NC, j = i % NC;
        sB[i] = (j < F) ? wl[k * F + j] : wr[k * F + (j - F)];
    }
    __syncthreads();

    int node = blockIdx.x * blockDim.x + threadIdx.x;
    if (node >= n) return;

    float xv[K];
    const float4* xr = reinterpret_cast<const float4*>(x + (size_t)node * K);
#pragma unroll
    for (int c = 0; c < K / 4; ++c) {
        float4 v = xr[c];
        xv[c * 4 + 0] = v.x; xv[c * 4 + 1] = v.y; xv[c * 4 + 2] = v.z; xv[c * 4 + 3] = v.w;
    }
    float acc[NC];
#pragma unroll
    for (int j = 0; j < NC; ++j) acc[j] = 0.f;
#pragma unroll
    for (int k = 0; k < K; ++k) {
        float a = xv[k];
#pragma unroll
        for (int j = 0; j < NC; ++j) acc[j] = fmaf(a, sB[k * NC + j], acc[j]);
    }
    float4* o = reinterpret_cast<float4*>(ylr + (size_t)node * NC);
#pragma unroll
    for (int c = 0; c < NC / 4; ++c)
        o[c] = make_float4(acc[c * 4], acc[c * 4 + 1], acc[c * 4 + 2], acc[c * 4 + 3]);
}

__global__ void proj3_pernode(const float* __restrict__ x, const float* __restrict__ wl,
                              const float* __restrict__ wr, float* __restrict__ ylr3, int n) {
    __shared__ float swl[16 * 9];
    __shared__ float swr[16 * 9];
    for (int i = threadIdx.x; i < 144; i += blockDim.x) {
        swl[i] = wl[i];
        swr[i] = wr[i];
    }
    __syncthreads();

    int node = blockIdx.x * blockDim.x + threadIdx.x;
    if (node >= n) return;

    float xv[16];
    const float4* xr = reinterpret_cast<const float4*>(x + (size_t)node * 16);
#pragma unroll
    for (int c = 0; c < 4; ++c) {
        float4 v = xr[c];
        xv[c * 4 + 0] = v.x; xv[c * 4 + 1] = v.y; xv[c * 4 + 2] = v.z; xv[c * 4 + 3] = v.w;
    }
    float al[9], ar[9];
#pragma unroll
    for (int j = 0; j < 9; ++j) { al[j] = 0.f; ar[j] = 0.f; }
#pragma unroll
    for (int k = 0; k < 16; ++k) {
        float a = xv[k];
#pragma unroll
        for (int j = 0; j < 9; ++j) {
            al[j] = fmaf(a, swl[k * 9 + j], al[j]);
            ar[j] = fmaf(a, swr[k * 9 + j], ar[j]);
        }
    }
    float4* o = reinterpret_cast<float4*>(ylr3 + (size_t)node * 32);
    o[0] = make_float4(al[0], al[1], al[2], al[3]);
    o[1] = make_float4(al[4], al[5], al[6], al[7]);
    o[2] = make_float4(al[8], 0.f, 0.f, 0.f);
    o[3] = make_float4(0.f, 0.f, 0.f, 0.f);
    o[4] = make_float4(ar[0], ar[1], ar[2], ar[3]);
    o[5] = make_float4(ar[4], ar[5], ar[6], ar[7]);
    ylr3[(size_t)node * 32 + 24] = ar[8];
}

// ---------------------------------------------------------------------------
// gather + combine (fused): warp per node.
// ---------------------------------------------------------------------------
template <int F, bool RELU>
__global__ void gather_combine(const float* __restrict__ ylr, const int* __restrict__ esrc,
                               const int* __restrict__ off, const int* __restrict__ cnt,
                               const float* __restrict__ bias, float* __restrict__ out, int n) {
    constexpr int CH = F / 4;
    constexpr int EPW = 32 / CH;
    int w = (blockIdx.x * blockDim.x + threadIdx.x) >> 5;
    if (w >= n) return;
    int lane = threadIdx.x & 31;
    int c = lane % CH, g = lane / CH;
    int start = off[w], deg = cnt[w];

    float4 acc = make_float4(0.f, 0.f, 0.f, 0.f);
    const float4* y4 = reinterpret_cast<const float4*>(ylr);
    for (int j = g; j < deg; j += EPW) {
        int s = __ldg(esrc + start + j);
        float4 v = y4[(size_t)s * (F / 2) + c];
        acc.x += v.x; acc.y += v.y; acc.z += v.z; acc.w += v.w;
    }
#pragma unroll
    for (int st = 16; st >= CH; st >>= 1) {
        acc.x += __shfl_xor_sync(0xFFFFFFFFu, acc.x, st);
        acc.y += __shfl_xor_sync(0xFFFFFFFFu, acc.y, st);
        acc.z += __shfl_xor_sync(0xFFFFFFFFu, acc.z, st);
        acc.w += __shfl_xor_sync(0xFFFFFFFFu, acc.w, st);
    }
    if (lane < CH) {
        float iv = __frcp_rn(fmaxf((float)deg, 1.0f));
        float4 r = y4[(size_t)w * (F / 2) + (F / 4) + c];
        float4 b = reinterpret_cast<const float4*>(bias)[c];
        float4 v;
        v.x = fmaf(acc.x, iv, r.x) + b.x;
        v.y = fmaf(acc.y, iv, r.y) + b.y;
        v.z = fmaf(acc.z, iv, r.z) + b.z;
        v.w = fmaf(acc.w, iv, r.w) + b.w;
        if (RELU) {
            v.x = fmaxf(v.x, 0.f); v.y = fmaxf(v.y, 0.f);
            v.z = fmaxf(v.z, 0.f); v.w = fmaxf(v.w, 0.f);
        }
        reinterpret_cast<float4*>(out)[(size_t)w * CH + c] = v;
    }
}

__global__ void gather9(const float* __restrict__ ylr3, const int* __restrict__ esrc,
                        const int* __restrict__ off, const int* __restrict__ cnt,
                        const float* __restrict__ bias, float* __restrict__ out, int n) {
    int w = (blockIdx.x * blockDim.x + threadIdx.x) >> 5;
    if (w >= n) return;
    int lane = threadIdx.x & 31;
    int c = lane % 4, g = lane / 4;
    int start = off[w], deg = cnt[w];

    float4 acc = make_float4(0.f, 0.f, 0.f, 0.f);
    const float4* y4 = reinterpret_cast<const float4*>(ylr3);
    for (int j = g; j < deg; j += 8) {
        int s = __ldg(esrc + start + j);
        float4 v = y4[(size_t)s * 8 + c];
        acc.x += v.x; acc.y += v.y; acc.z += v.z; acc.w += v.w;
    }
#pragma unroll
    for (int st = 16; st >= 4; st >>= 1) {
        acc.x += __shfl_xor_sync(0xFFFFFFFFu, acc.x, st);
        acc.y += __shfl_xor_sync(0xFFFFFFFFu, acc.y, st);
        acc.z += __shfl_xor_sync(0xFFFFFFFFu, acc.z, st);
        acc.w += __shfl_xor_sync(0xFFFFFFFFu, acc.w, st);
    }
    if (lane < 4) {
        float iv = __frcp_rn(fmaxf((float)deg, 1.0f));
        float a[4] = {acc.x, acc.y, acc.z, acc.w};
#pragma unroll
        for (int t = 0; t < 4; ++t) {
            int j = c * 4 + t;
            if (j < 9) {
                float yr = ylr3[(size_t)w * 32 + 16 + j];
                out[(size_t)w * 9 + j] = fmaf(a[t], iv, yr + __ldg(bias + j));
            }
        }
    }
}

// ---------------------------------------------------------------------------
// launch
// ---------------------------------------------------------------------------
extern "C" void kernel_launch(void* const* d_in, const int* in_sizes, int n_in,
                              void* d_out, int out_size) {
    const float* emb = (const float*)d_in[0];
    const int* ei = (const int*)d_in[1];
    const float* wl0 = (const float*)d_in[3];
    const float* wr0 = (const float*)d_in[4];
    const float* b0  = (const float*)d_in[5];
    const float* wl1 = (const float*)d_in[6];
    const float* wr1 = (const float*)d_in[7];
    const float* b1  = (const float*)d_in[8];
    const float* wl2 = (const float*)d_in[9];
    const float* wr2 = (const float*)d_in[10];
    const float* b2  = (const float*)d_in[11];
    const float* wl3 = (const float*)d_in[12];
    const float* wr3 = (const float*)d_in[13];
    const float* b3  = (const float*)d_in[14];
    float* out = (float*)d_out;

    const int n = in_sizes[0] / 128;
    const int E = in_sizes[1] / 2;
    const int* src = ei;
    const int* dst = ei + E;

    float *ylr, *xbuf;
    unsigned *xh, *xl;
    unsigned short *wth, *wtl;
    int *cnt, *off, *cur, *esrc, *bsum;
    cudaGetSymbolAddress((void**)&ylr, g_ylr);
    cudaGetSymbolAddress((void**)&xbuf, g_x);
    cudaGetSymbolAddress((void**)&xh, g_xh);
    cudaGetSymbolAddress((void**)&xl, g_xl);
    cudaGetSymbolAddress((void**)&wth, g_wth);
    cudaGetSymbolAddress((void**)&wtl, g_wtl);
    cudaGetSymbolAddress((void**)&cnt, g_cnt);
    cudaGetSymbolAddress((void**)&off, g_off);
    cudaGetSymbolAddress((void**)&cur, g_cur);
    cudaGetSymbolAddress((void**)&esrc, g_esrc);
    cudaGetSymbolAddress((void**)&bsum, g_bsum);

    auto cdiv = [](int a, int b) { return (a + b - 1) / b; };
    const int TB = 256;
    const int nb = cdiv(n, 512);

    const int SM_MMA = 4 * 128 * 136 * 2;               // 139264
    const int SM1 = (2 * 128 * 36 + 2 * 32 * 64) * 4;   // 53248
    cudaFuncSetAttribute((const void*)mma_proj0,
                         cudaFuncAttributeMaxDynamicSharedMemorySize, SM_MMA);
    cudaFuncSetAttribute((const void*)sgemm_proj_x2<64, 64, 128, 32, 4>,
                         cudaFuncAttributeMaxDynamicSharedMemorySize, SM1);

    static cudaStream_t s2 = nullptr;
    static cudaEvent_t evFork = nullptr, evJoin = nullptr;
    if (!s2) {
        cudaStreamCreateWithFlags(&s2, cudaStreamNonBlocking);
        cudaEventCreateWithFlags(&evFork, cudaEventDisableTiming);
        cudaEventCreateWithFlags(&evJoin, cudaEventDisableTiming);
    }

    // ---- fork: CSR build on s2 ----
    cudaEventRecord(evFork, 0);
    cudaStreamWaitEvent(s2, evFork, 0);

    zero_int<<<cdiv(n, 512), 512, 0, s2>>>(cnt, n);
    hist_kernel<<<cdiv(E, 512), 512, 0, s2>>>(dst, cnt, E);
    scan_block<<<nb, 512, 0, s2>>>(cnt, off, bsum, n);
    scan_sums<<<1, 512, 0, s2>>>(bsum, nb);
    scan_add<<<nb, 512, 0, s2>>>(off, bsum, cur, n);
    fill_kernel<<<cdiv(E, 512), 512, 0, s2>>>(src, dst, cur, esrc, E);
    cudaEventRecord(evJoin, s2);

    // ---- main: layer-0 tensor-core GEMM (with bf16 split conversions) ----
    cvt_w_kernel<<<64, 256>>>(wl0, wr0, wth, wtl);
    cvt_x_kernel<<<cdiv(n * 32, 256), 256>>>((const float4*)emb, (uint2*)xh, (uint2*)xl,
                                             n * 32);
    mma_proj0<<<cdiv(n, 128), 256, SM_MMA>>>((const unsigned short*)xh,
                                             (const unsigned short*)xl, wth, wtl, ylr, n);

    // ---- join ----
    cudaStreamWaitEvent(0, evJoin, 0);

    gather_combine<64, true><<<cdiv(n * 32, TB), TB>>>(ylr, esrc, off, cnt, b0, xbuf, n);

    sgemm_proj_x2<64, 64, 128, 32, 4><<<cdiv(n, 128), 128, SM1>>>(xbuf, wl1, wr1, ylr, n);
    gather_combine<32, true><<<cdiv(n * 32, TB), TB>>>(ylr, esrc, off, cnt, b1, xbuf, n);

    proj_pernode<32, 16><<<cdiv(n, TB), TB>>>(xbuf, wl2, wr2, ylr, n);
    gather_combine<16, true><<<cdiv(n * 32, TB), TB>>>(ylr, esrc, off, cnt, b2, xbuf, n);

    proj3_pernode<<<cdiv(n, TB), TB>>>(xbuf, wl3, wr3, ylr, n);
    gather9<<<cdiv(n * 32, TB), TB>>>(ylr, esrc, off, cnt, b3, out, n);
}